// round 2
// baseline (speedup 1.0000x reference)
#include <cuda_runtime.h>

// ---------------------------------------------------------------------------
// Problem constants
// ---------------------------------------------------------------------------
#define HH 80
#define WW 96
#define TTT 112
#define NS (HH*WW*TTT)        // 860160 voxels
#define NC 16
#define NCC 59                // 2*C + 27
#define FH 40
#define FW 48
#define FT 56
// extended box(y) grid: centers in [-2, H+2) etc.
#define PH 84
#define PW 100
#define PT 116
#define NSP (PH*PW*PT)        // 974400

// ---------------------------------------------------------------------------
// Scratch (device globals; no allocation allowed)
// ---------------------------------------------------------------------------
__device__ float g_stack[NCC*NS];   // [xw(16) | corr(27) | y(16)]
__device__ float g_pm[NC*NS];       // box3(xw), centered
__device__ float g_pf[NC*NSP];      // box3(y), centered, extended grid
__device__ float g_t1[NCC*NS];      // conv1a out
__device__ float g_h [NC*NS];       // h
__device__ float g_t2[NC*NS];       // conv2a out
__device__ float g_hr[NC*NS];       // h + res

__device__ float2 g_wp1a[NCC*27*30];
__device__ float2 g_wp1b[NCC*27*8];
__device__ float2 g_wp2a[NC*27*8];
__device__ float2 g_wp2b[NC*27*8];
__device__ float2 g_wpf [NC*27*2];

// ---------------------------------------------------------------------------
// Weight repack: w[Cout][Cin][27] -> wp[ci][tap][co_pair] (float2, zero pad)
// ---------------------------------------------------------------------------
__global__ void repack_kernel(const float* __restrict__ w, int which,
                              int cout, int cin, int cpairs)
{
    float2* wp;
    switch (which) {
        case 0: wp = g_wp1a; break;
        case 1: wp = g_wp1b; break;
        case 2: wp = g_wp2a; break;
        case 3: wp = g_wp2b; break;
        default: wp = g_wpf; break;
    }
    int idx = blockIdx.x*256 + threadIdx.x;
    int total = cin*27*cpairs;
    if (idx >= total) return;
    int cp  = idx % cpairs;
    int tap = (idx / cpairs) % 27;
    int ci  = idx / (cpairs*27);
    int co0 = 2*cp, co1 = 2*cp+1;
    float a = (co0 < cout) ? w[(co0*cin + ci)*27 + tap] : 0.0f;
    float b = (co1 < cout) ? w[(co1*cin + ci)*27 + tap] : 0.0f;
    wp[idx] = make_float2(a, b);
}

// ---------------------------------------------------------------------------
// Fused: flow upsample (align_corners, x2) + grid_sample(x) + copy y -> stack
// ---------------------------------------------------------------------------
__global__ void warp_kernel(const float* __restrict__ x,
                            const float* __restrict__ y,
                            const float* __restrict__ flow)
{
    int idx = blockIdx.x*256 + threadIdx.x;
    if (idx >= NS) return;
    int t = idx % TTT;
    int w = (idx / TTT) % WW;
    int h = idx / (TTT*WW);

    // trilinear upsample of flow (align_corners=True), scaled by 2
    float ph = h * (39.0f/79.0f);
    float pw = w * (47.0f/95.0f);
    float pt = t * (55.0f/111.0f);
    int ih = (int)ph; if (ih > FH-2) ih = FH-2;
    int iw = (int)pw; if (iw > FW-2) iw = FW-2;
    int it = (int)pt; if (it > FT-2) it = FT-2;
    float fh = ph - (float)ih;
    float fw = pw - (float)iw;
    float ft = pt - (float)it;

    float fu[3];
    #pragma unroll
    for (int c = 0; c < 3; c++) {
        const float* fc = flow + c*(FH*FW*FT) + (ih*FW + iw)*FT + it;
        float v000 = fc[0],        v001 = fc[1];
        float v010 = fc[FT],       v011 = fc[FT+1];
        float v100 = fc[FW*FT],    v101 = fc[FW*FT+1];
        float v110 = fc[FW*FT+FT], v111 = fc[FW*FT+FT+1];
        float a0 = v000*(1.0f-ft) + v001*ft;
        float a1 = v010*(1.0f-ft) + v011*ft;
        float a2 = v100*(1.0f-ft) + v101*ft;
        float a3 = v110*(1.0f-ft) + v111*ft;
        float b0 = a0*(1.0f-fw) + a1*fw;
        float b1 = a2*(1.0f-fw) + a3*fw;
        fu[c] = 2.0f*(b0*(1.0f-fh) + b1*fh);
    }

    // grid_sample of x, zeros padding, coords in voxel units
    float cx = (float)h + fu[0];
    float cy = (float)w + fu[1];
    float cz = (float)t + fu[2];
    float x0f = floorf(cx), y0f = floorf(cy), z0f = floorf(cz);
    float fx = cx - x0f, fy = cy - y0f, fz = cz - z0f;
    int x0 = (int)x0f, y0 = (int)y0f, z0 = (int)z0f;

    float acc[NC];
    #pragma unroll
    for (int c = 0; c < NC; c++) acc[c] = 0.0f;

    #pragma unroll
    for (int dx = 0; dx < 2; dx++)
    #pragma unroll
    for (int dy = 0; dy < 2; dy++)
    #pragma unroll
    for (int dz = 0; dz < 2; dz++) {
        int ix = x0+dx, iy = y0+dy, iz = z0+dz;
        if (ix < 0 || ix >= HH || iy < 0 || iy >= WW || iz < 0 || iz >= TTT) continue;
        float wgt = (dx ? fx : 1.0f-fx) * (dy ? fy : 1.0f-fy) * (dz ? fz : 1.0f-fz);
        const float* xp = x + (ix*WW + iy)*TTT + iz;
        #pragma unroll
        for (int c = 0; c < NC; c++) acc[c] += wgt * xp[c*NS];
    }

    #pragma unroll
    for (int c = 0; c < NC; c++) {
        g_stack[c*NS + idx]        = acc[c];
        g_stack[(43+c)*NS + idx]   = y[c*NS + idx];
    }
}

// ---------------------------------------------------------------------------
// box3 of xw (stack ch 0..15), centered, zero pad -> g_pm
// ---------------------------------------------------------------------------
__global__ void box_pm_kernel()
{
    int idx = blockIdx.x*256 + threadIdx.x;
    int c = blockIdx.y;
    if (idx >= NS) return;
    int t = idx % TTT;
    int w = (idx / TTT) % WW;
    int h = idx / (TTT*WW);
    const float* s = g_stack + c*NS;
    float acc = 0.0f;
    #pragma unroll
    for (int dh = -1; dh <= 1; dh++) {
        int gh = h + dh; if ((unsigned)gh >= HH) continue;
        #pragma unroll
        for (int dw = -1; dw <= 1; dw++) {
            int gw = w + dw; if ((unsigned)gw >= WW) continue;
            const float* row = s + (gh*WW + gw)*TTT;
            #pragma unroll
            for (int dt = -1; dt <= 1; dt++) {
                int gt = t + dt; if ((unsigned)gt >= TTT) continue;
                acc += row[gt];
            }
        }
    }
    g_pm[c*NS + idx] = acc;
}

// ---------------------------------------------------------------------------
// box3 of y, centered, on extended grid (center = coord - 2) -> g_pf
// ---------------------------------------------------------------------------
__global__ void box_pf_kernel(const float* __restrict__ y)
{
    int idx = blockIdx.x*256 + threadIdx.x;
    int c = blockIdx.y;
    if (idx >= NSP) return;
    int d = idx % PT;
    int b = (idx / PT) % PW;
    int a = idx / (PT*PW);
    int hc = a - 2, wc = b - 2, tc = d - 2;
    const float* s = y + c*NS;
    float acc = 0.0f;
    #pragma unroll
    for (int dh = -1; dh <= 1; dh++) {
        int gh = hc + dh; if ((unsigned)gh >= HH) continue;
        #pragma unroll
        for (int dw = -1; dw <= 1; dw++) {
            int gw = wc + dw; if ((unsigned)gw >= WW) continue;
            const float* row = s + (gh*WW + gw)*TTT;
            #pragma unroll
            for (int dt = -1; dt <= 1; dt++) {
                int gt = tc + dt; if ((unsigned)gt >= TTT) continue;
                acc += row[gt];
            }
        }
    }
    g_pf[c*NSP + idx] = acc;
}

// ---------------------------------------------------------------------------
// correlation: corr[o] = (1/27) sum_c pm[c] * pf_ext[c, voxel + (2i-2,2j-2,2k-2)]
// writes stack channels 16..42
// ---------------------------------------------------------------------------
__global__ void corr_kernel()
{
    int idx = blockIdx.x*128 + threadIdx.x;
    if (idx >= NS) return;
    int t = idx % TTT;
    int w = (idx / TTT) % WW;
    int h = idx / (TTT*WW);

    float pm[NC];
    #pragma unroll
    for (int c = 0; c < NC; c++) pm[c] = g_pm[c*NS + idx];

    int o = 0;
    for (int i = 0; i < 3; i++)
    for (int j = 0; j < 3; j++)
    for (int k = 0; k < 3; k++) {
        const float* p = g_pf + ((h + 2*i)*PW + (w + 2*j))*PT + (t + 2*k);
        float acc = 0.0f;
        #pragma unroll
        for (int c = 0; c < NC; c++) acc += pm[c] * p[c*NSP];
        g_stack[(16 + o)*NS + idx] = acc * (1.0f/27.0f);
        o++;
    }
}

// ---------------------------------------------------------------------------
// Direct 3x3x3 conv, pad 1. Tile 4(H)x8(W)x8(T), 256 threads, one voxel/thread.
// All Cout accumulated as f32x2 pairs (packed FFMA2). Weights pre-packed
// [ci][tap][co_pair] so the inner loop is broadcast LDS.64 + fma.rn.f32x2.
// ---------------------------------------------------------------------------
template<int CIN, int CP, int COUT, bool RELU, bool ADD>
__global__ void __launch_bounds__(256)
conv3_kernel(const float* __restrict__ in, const float2* __restrict__ wp,
             const float* __restrict__ bias, const float* __restrict__ addsrc,
             float* __restrict__ out)
{
    __shared__ float  s_in[6*10*10];
    __shared__ float2 s_w[27*CP];
    const int tid = threadIdx.x;
    const int t0 = blockIdx.x*8, w0 = blockIdx.y*8, h0 = blockIdx.z*4;
    const int lt = tid & 7, lw = (tid >> 3) & 7, lh = tid >> 6;

    unsigned long long acc[CP];
    #pragma unroll
    for (int i = 0; i < CP; i++) acc[i] = 0ull;

    for (int ci = 0; ci < CIN; ci++) {
        __syncthreads();
        const float* inc = in + ci*NS;
        for (int i = tid; i < 600; i += 256) {
            int it = i % 10, iw = (i/10) % 10, ih = i/100;
            int gh = h0 + ih - 1, gw = w0 + iw - 1, gt = t0 + it - 1;
            float v = 0.0f;
            if ((unsigned)gh < HH && (unsigned)gw < WW && (unsigned)gt < TTT)
                v = inc[(gh*WW + gw)*TTT + gt];
            s_in[i] = v;
        }
        const float2* wc = wp + ci*27*CP;
        for (int i = tid; i < 27*CP; i += 256) s_w[i] = wc[i];
        __syncthreads();

        const unsigned long long* wq = reinterpret_cast<const unsigned long long*>(s_w);
        #pragma unroll
        for (int tap = 0; tap < 27; tap++) {
            const int dt = tap % 3, dw = (tap/3) % 3, dh = tap/9;
            float v = s_in[((lh+dh)*10 + (lw+dw))*10 + (lt+dt)];
            unsigned int vu = __float_as_uint(v);
            unsigned long long vv;
            asm("mov.b64 %0, {%1, %1};" : "=l"(vv) : "r"(vu));
            #pragma unroll
            for (int cp = 0; cp < CP; cp++) {
                asm("fma.rn.f32x2 %0, %1, %2, %0;"
                    : "+l"(acc[cp]) : "l"(wq[tap*CP + cp]), "l"(vv));
            }
        }
    }

    const int vox = ((h0+lh)*WW + (w0+lw))*TTT + (t0+lt);
    #pragma unroll
    for (int cp = 0; cp < CP; cp++) {
        float r0 = __uint_as_float((unsigned int)(acc[cp] & 0xffffffffull));
        float r1 = __uint_as_float((unsigned int)(acc[cp] >> 32));
        const int co0 = 2*cp, co1 = 2*cp+1;
        if (co0 < COUT) {
            float r = r0 + bias[co0];
            if (RELU) r = fmaxf(r, 0.0f);
            if (ADD)  r += addsrc[co0*NS + vox];
            out[co0*NS + vox] = r;
        }
        if (co1 < COUT) {
            float r = r1 + bias[co1];
            if (RELU) r = fmaxf(r, 0.0f);
            if (ADD)  r += addsrc[co1*NS + vox];
            out[co1*NS + vox] = r;
        }
    }
}

// ---------------------------------------------------------------------------
// Launch
// ---------------------------------------------------------------------------
extern "C" void kernel_launch(void* const* d_in, const int* in_sizes, int n_in,
                              void* d_out, int out_size)
{
    const float* x    = (const float*)d_in[0];
    const float* y    = (const float*)d_in[1];
    const float* flow = (const float*)d_in[2];
    const float* w1a  = (const float*)d_in[3];
    const float* b1a  = (const float*)d_in[4];
    const float* w1b  = (const float*)d_in[5];
    const float* b1b  = (const float*)d_in[6];
    const float* w2a  = (const float*)d_in[7];
    const float* b2a  = (const float*)d_in[8];
    const float* w2b  = (const float*)d_in[9];
    const float* b2b  = (const float*)d_in[10];
    const float* wf   = (const float*)d_in[11];
    const float* bf   = (const float*)d_in[12];
    float* out = (float*)d_out;

    void *p_stack, *p_t1, *p_h, *p_t2, *p_hr;
    void *p_wp1a, *p_wp1b, *p_wp2a, *p_wp2b, *p_wpf;
    cudaGetSymbolAddress(&p_stack, g_stack);
    cudaGetSymbolAddress(&p_t1,    g_t1);
    cudaGetSymbolAddress(&p_h,     g_h);
    cudaGetSymbolAddress(&p_t2,    g_t2);
    cudaGetSymbolAddress(&p_hr,    g_hr);
    cudaGetSymbolAddress(&p_wp1a,  g_wp1a);
    cudaGetSymbolAddress(&p_wp1b,  g_wp1b);
    cudaGetSymbolAddress(&p_wp2a,  g_wp2a);
    cudaGetSymbolAddress(&p_wp2b,  g_wp2b);
    cudaGetSymbolAddress(&p_wpf,   g_wpf);

    // weight repack
    repack_kernel<<<(NCC*27*30 + 255)/256, 256>>>(w1a, 0, 59, 59, 30);
    repack_kernel<<<(NCC*27*8  + 255)/256, 256>>>(w1b, 1, 16, 59, 8);
    repack_kernel<<<(NC*27*8   + 255)/256, 256>>>(w2a, 2, 16, 16, 8);
    repack_kernel<<<(NC*27*8   + 255)/256, 256>>>(w2b, 3, 16, 16, 8);
    repack_kernel<<<(NC*27*2   + 255)/256, 256>>>(wf,  4,  3, 16, 2);

    // upsample + warp + y copy
    warp_kernel<<<(NS + 255)/256, 256>>>(x, y, flow);

    // box sums
    box_pm_kernel<<<dim3((NS + 255)/256, NC), 256>>>();
    box_pf_kernel<<<dim3((NSP + 255)/256, NC), 256>>>(y);

    // correlation -> stack ch 16..42
    corr_kernel<<<(NS + 127)/128, 128>>>();

    dim3 cgrid(TTT/8, WW/8, HH/4);   // 14, 12, 20

    // conv1a: stack(59) -> t1(59), no act
    conv3_kernel<59,30,59,false,false><<<cgrid, 256>>>(
        (const float*)p_stack, (const float2*)p_wp1a, b1a, nullptr, (float*)p_t1);
    // conv1b: t1(59) -> h(16), relu
    conv3_kernel<59,8,16,true,false><<<cgrid, 256>>>(
        (const float*)p_t1, (const float2*)p_wp1b, b1b, nullptr, (float*)p_h);
    // conv2a: h -> t2, no act
    conv3_kernel<16,8,16,false,false><<<cgrid, 256>>>(
        (const float*)p_h, (const float2*)p_wp2a, b2a, nullptr, (float*)p_t2);
    // conv2b: hr = h + relu(conv(t2))
    conv3_kernel<16,8,16,true,true><<<cgrid, 256>>>(
        (const float*)p_t2, (const float2*)p_wp2b, b2b, (const float*)p_h, (float*)p_hr);
    // convf: out = conv(hr, wf) + bf
    conv3_kernel<16,2,3,false,false><<<cgrid, 256>>>(
        (const float*)p_hr, (const float2*)p_wpf, bf, nullptr, out);
}

// round 4
// speedup vs baseline: 1.8631x; 1.8631x over previous
#include <cuda_runtime.h>
#include <cuda_bf16.h>
#include <cstdint>

#define HH 80
#define WW 96
#define TTT 112
#define NS (HH*WW*TTT)
#define NC 16
#define NCC 59
#define FH 40
#define FW 48
#define FT 56
#define PH 84
#define PW 100
#define PT 116
#define NSP (PH*PW*PT)

// scratch
__device__ float g_stack[NCC*NS];
__device__ float g_pm[NC*NS];
__device__ float g_pf[NC*NSP];
__device__ float g_t1[NCC*NS];
__device__ float g_h [NC*NS];
__device__ float g_t2[NC*NS];
__device__ float g_hr[NC*NS];

// B in mma-fragment order: [iter36][ks3][nt][lane32] -> uint4 (b0h,b1h,b0l,b1l)
__device__ uint4 g_Bf1a[36*3*8*32];   // conv1a: NT=8
__device__ uint4 g_Bf1b[36*3*2*32];   // conv1b: NT=2

__device__ float2 g_wp2a[NC*27*8];
__device__ float2 g_wp2b[NC*27*8];
__device__ float2 g_wpf [NC*27*2];

// ---- helpers ----
// split fp32 pair -> hi bf16x2 (truncated), lo bf16x2 (rounded exact residual)
// low 16 bits of result = first value
__device__ __forceinline__ void split_pair(float v0, float v1, uint32_t& hi, uint32_t& lo) {
    uint32_t u0 = __float_as_uint(v0), u1 = __float_as_uint(v1);
    asm("prmt.b32 %0, %1, %2, 0x7632;" : "=r"(hi) : "r"(u0), "r"(u1));
    float h0 = __uint_as_float(u0 & 0xffff0000u);
    float h1 = __uint_as_float(u1 & 0xffff0000u);
    float l0 = v0 - h0, l1 = v1 - h1;
    asm("cvt.rn.satfinite.bf16x2.f32 %0, %1, %2;" : "=r"(lo) : "f"(l1), "f"(l0));
}

__device__ __forceinline__ void mma_bf16(float* c, const uint32_t* a, uint32_t b0, uint32_t b1) {
    asm volatile("mma.sync.aligned.m16n8k16.row.col.f32.bf16.bf16.f32 "
        "{%0,%1,%2,%3}, {%4,%5,%6,%7}, {%8,%9}, {%0,%1,%2,%3};"
        : "+f"(c[0]), "+f"(c[1]), "+f"(c[2]), "+f"(c[3])
        : "r"(a[0]), "r"(a[1]), "r"(a[2]), "r"(a[3]), "r"(b0), "r"(b1));
}

// ---------------------------------------------------------------------------
// merged repack: B fragments (conv1a, conv1b) + f32 packs (conv2a/2b/f)
// ranges: [0,27648) 1a frags  [27648,34560) 1b frags  [34560,42336) f32 packs
// ---------------------------------------------------------------------------
__global__ void repack_all(const float* __restrict__ w1a, const float* __restrict__ w1b,
                           const float* __restrict__ w2a, const float* __restrict__ w2b,
                           const float* __restrict__ wf)
{
    int gi = blockIdx.x*256 + threadIdx.x;
    if (gi < 34560) {
        bool is1a = gi < 27648;
        int idx = is1a ? gi : gi - 27648;
        int NT   = is1a ? 8 : 2;
        int cout = is1a ? 59 : 16;
        const float* w = is1a ? w1a : w1b;
        uint4* dst = is1a ? g_Bf1a : g_Bf1b;

        int lane = idx & 31;
        int nt   = (idx >> 5) % NT;
        int ks   = (idx / (32*NT)) % 3;
        int iter = idx / (96*NT);
        int tap = iter >> 2, chunk = iter & 3;
        int n = nt*8 + (lane >> 2);
        int q = lane & 3;
        int k0 = ks*16 + q*2;
        int dh = tap/3, dw = tap%3;

        float v[4];
        #pragma unroll
        for (int j = 0; j < 4; j++) {
            int k = k0 + (j >> 1)*8 + (j & 1);
            int cil = k/3, dt = k - 3*cil;
            int ci = chunk*16 + cil;
            float val = 0.0f;
            if (ci < NCC && n < cout)
                val = w[(n*NCC + ci)*27 + dh*9 + dw*3 + dt];
            v[j] = val;
        }
        uint32_t h0, l0, h1, l1;
        split_pair(v[0], v[1], h0, l0);
        split_pair(v[2], v[3], h1, l1);
        dst[idx] = make_uint4(h0, h1, l0, l1);
    } else {
        int idx = gi - 34560;
        const float* w; float2* wp; int cout, cin, cp;
        if (idx < 3456)      { w = w2a; wp = g_wp2a; cout = 16; cin = 16; cp = 8; }
        else if (idx < 6912) { w = w2b; wp = g_wp2b; cout = 16; cin = 16; cp = 8; idx -= 3456; }
        else if (idx < 7776) { w = wf;  wp = g_wpf;  cout = 3;  cin = 16; cp = 2; idx -= 6912; }
        else return;
        int cpi = idx % cp;
        int tap = (idx / cp) % 27;
        int ci  = idx / (cp*27);
        int co0 = 2*cpi, co1 = 2*cpi + 1;
        float a = (co0 < cout) ? w[(co0*cin + ci)*27 + tap] : 0.0f;
        float c = (co1 < cout) ? w[(co1*cin + ci)*27 + tap] : 0.0f;
        wp[idx] = make_float2(a, c);
    }
}

// ---------------------------------------------------------------------------
// warp / box / corr  (proven in R1)
// ---------------------------------------------------------------------------
__global__ void warp_kernel(const float* __restrict__ x, const float* __restrict__ y,
                            const float* __restrict__ flow)
{
    int idx = blockIdx.x*256 + threadIdx.x;
    if (idx >= NS) return;
    int t = idx % TTT, w = (idx / TTT) % WW, h = idx / (TTT*WW);

    float ph = h * (39.0f/79.0f), pw = w * (47.0f/95.0f), pt = t * (55.0f/111.0f);
    int ih = (int)ph; if (ih > FH-2) ih = FH-2;
    int iw = (int)pw; if (iw > FW-2) iw = FW-2;
    int it = (int)pt; if (it > FT-2) it = FT-2;
    float fh = ph - (float)ih, fw = pw - (float)iw, ft = pt - (float)it;

    float fu[3];
    #pragma unroll
    for (int c = 0; c < 3; c++) {
        const float* fc = flow + c*(FH*FW*FT) + (ih*FW + iw)*FT + it;
        float v000 = fc[0],        v001 = fc[1];
        float v010 = fc[FT],       v011 = fc[FT+1];
        float v100 = fc[FW*FT],    v101 = fc[FW*FT+1];
        float v110 = fc[FW*FT+FT], v111 = fc[FW*FT+FT+1];
        float a0 = v000*(1.0f-ft) + v001*ft;
        float a1 = v010*(1.0f-ft) + v011*ft;
        float a2 = v100*(1.0f-ft) + v101*ft;
        float a3 = v110*(1.0f-ft) + v111*ft;
        float b0 = a0*(1.0f-fw) + a1*fw;
        float b1 = a2*(1.0f-fw) + a3*fw;
        fu[c] = 2.0f*(b0*(1.0f-fh) + b1*fh);
    }

    float cx = (float)h + fu[0], cy = (float)w + fu[1], cz = (float)t + fu[2];
    float x0f = floorf(cx), y0f = floorf(cy), z0f = floorf(cz);
    float fx = cx - x0f, fy = cy - y0f, fz = cz - z0f;
    int x0 = (int)x0f, y0 = (int)y0f, z0 = (int)z0f;

    float acc[NC];
    #pragma unroll
    for (int c = 0; c < NC; c++) acc[c] = 0.0f;
    #pragma unroll
    for (int dx = 0; dx < 2; dx++)
    #pragma unroll
    for (int dy = 0; dy < 2; dy++)
    #pragma unroll
    for (int dz = 0; dz < 2; dz++) {
        int ix = x0+dx, iy = y0+dy, iz = z0+dz;
        if (ix < 0 || ix >= HH || iy < 0 || iy >= WW || iz < 0 || iz >= TTT) continue;
        float wgt = (dx ? fx : 1.0f-fx) * (dy ? fy : 1.0f-fy) * (dz ? fz : 1.0f-fz);
        const float* xp = x + (ix*WW + iy)*TTT + iz;
        #pragma unroll
        for (int c = 0; c < NC; c++) acc[c] += wgt * xp[c*NS];
    }
    #pragma unroll
    for (int c = 0; c < NC; c++) {
        g_stack[c*NS + idx]      = acc[c];
        g_stack[(43+c)*NS + idx] = y[c*NS + idx];
    }
}

__global__ void box_pm_kernel()
{
    int idx = blockIdx.x*256 + threadIdx.x;
    int c = blockIdx.y;
    if (idx >= NS) return;
    int t = idx % TTT, w = (idx / TTT) % WW, h = idx / (TTT*WW);
    const float* s = g_stack + c*NS;
    float acc = 0.0f;
    #pragma unroll
    for (int dh = -1; dh <= 1; dh++) {
        int gh = h + dh; if ((unsigned)gh >= HH) continue;
        #pragma unroll
        for (int dw = -1; dw <= 1; dw++) {
            int gw = w + dw; if ((unsigned)gw >= WW) continue;
            const float* row = s + (gh*WW + gw)*TTT;
            #pragma unroll
            for (int dt = -1; dt <= 1; dt++) {
                int gt = t + dt; if ((unsigned)gt >= TTT) continue;
                acc += row[gt];
            }
        }
    }
    g_pm[c*NS + idx] = acc;
}

__global__ void box_pf_kernel(const float* __restrict__ y)
{
    int idx = blockIdx.x*256 + threadIdx.x;
    int c = blockIdx.y;
    if (idx >= NSP) return;
    int d = idx % PT, b = (idx / PT) % PW, a = idx / (PT*PW);
    int hc = a - 2, wc = b - 2, tc = d - 2;
    const float* s = y + c*NS;
    float acc = 0.0f;
    #pragma unroll
    for (int dh = -1; dh <= 1; dh++) {
        int gh = hc + dh; if ((unsigned)gh >= HH) continue;
        #pragma unroll
        for (int dw = -1; dw <= 1; dw++) {
            int gw = wc + dw; if ((unsigned)gw >= WW) continue;
            const float* row = s + (gh*WW + gw)*TTT;
            #pragma unroll
            for (int dt = -1; dt <= 1; dt++) {
                int gt = tc + dt; if ((unsigned)gt >= TTT) continue;
                acc += row[gt];
            }
        }
    }
    g_pf[c*NSP + idx] = acc;
}

__global__ void corr_kernel()
{
    int idx = blockIdx.x*128 + threadIdx.x;
    if (idx >= NS) return;
    int t = idx % TTT, w = (idx / TTT) % WW, h = idx / (TTT*WW);
    float pm[NC];
    #pragma unroll
    for (int c = 0; c < NC; c++) pm[c] = g_pm[c*NS + idx];
    int o = 0;
    for (int i = 0; i < 3; i++)
    for (int j = 0; j < 3; j++)
    for (int k = 0; k < 3; k++) {
        const float* p = g_pf + ((h + 2*i)*PW + (w + 2*j))*PT + (t + 2*k);
        float acc = 0.0f;
        #pragma unroll
        for (int c = 0; c < NC; c++) acc += pm[c] * p[c*NSP];
        g_stack[(16 + o)*NS + idx] = acc * (1.0f/27.0f);
        o++;
    }
}

// ---------------------------------------------------------------------------
// warp-MMA implicit-GEMM 3x3x3 conv, split-bf16 3-product.
// CTA = one (h,w), M=112 (7 warps x m16), N = NT*8, K-loop 9 taps x 4 chunks.
// ---------------------------------------------------------------------------
template<int NT, int COUT, bool RELU>
__global__ void __launch_bounds__(256)
conv_mma(const float* __restrict__ in, const uint4* __restrict__ Bf,
         const float* __restrict__ bias, float* __restrict__ out)
{
    __shared__ float s_strip[16*121 + 8];
    __shared__ uint4 s_B[3*NT*32];

    const int tid = threadIdx.x, wid = tid >> 5, lane = tid & 31;
    const int w = blockIdx.x, h = blockIdx.y;
    const int q = lane & 3, r = lane >> 2;

    float acc[NT][4];
    #pragma unroll
    for (int nt = 0; nt < NT; nt++)
        #pragma unroll
        for (int j = 0; j < 4; j++) acc[nt][j] = 0.0f;

    for (int iter = 0; iter < 36; iter++) {
        const int tap = iter >> 2, chunk = iter & 3;
        const int gh = h + tap/3 - 1, gw = w + tap%3 - 1;
        const bool rowok = ((unsigned)gh < HH) && ((unsigned)gw < WW);
        const float* rowptr = in + (gh*WW + gw)*TTT;

        __syncthreads();
        // stage 16 input strips (t = -1..112, zero pad outside)
        for (int i = tid; i < 16*114; i += 256) {
            int cil = i / 114, tt = i - cil*114;
            int ci = chunk*16 + cil;
            int t = tt - 1;
            float v = 0.0f;
            if (rowok && ci < NCC && (unsigned)t < TTT) v = rowptr[ci*NS + t];
            s_strip[cil*121 + tt] = v;
        }
        // stage B fragments
        {
            const uint4* src = Bf + iter*(3*NT*32);
            #pragma unroll
            for (int i = tid; i < 3*NT*32; i += 256) s_B[i] = src[i];
        }
        __syncthreads();

        if (wid < 7) {
            const int m0 = wid*16 + r;
            uint32_t aH[3][4], aL[3][4];
            #pragma unroll
            for (int ks = 0; ks < 3; ks++) {
                const int kb = ks*16 + q*2;
                #pragma unroll
                for (int half = 0; half < 2; half++) {
                    int k  = kb + half*8;
                    int c0 = (k*171) >> 9,  d0 = k - 3*c0;
                    int k1 = k + 1;
                    int c1 = (k1*171) >> 9, d1 = k1 - 3*c1;
                    float v00 = s_strip[c0*121 + m0 + d0];
                    float v01 = s_strip[c1*121 + m0 + d1];
                    float v10 = s_strip[c0*121 + m0 + 8 + d0];
                    float v11 = s_strip[c1*121 + m0 + 8 + d1];
                    split_pair(v00, v01, aH[ks][half*2+0], aL[ks][half*2+0]);
                    split_pair(v10, v11, aH[ks][half*2+1], aL[ks][half*2+1]);
                }
                // reorder to mma register order: {a0,a1,a2,a3} = {(r,k),(r+8,k),(r,k+8),(r+8,k+8)}
                // half=0 wrote slots 0,1 ; half=1 wrote slots 2,3  -> already correct
            }
            #pragma unroll
            for (int ks = 0; ks < 3; ks++) {
                #pragma unroll
                for (int nt = 0; nt < NT; nt++) {
                    uint4 B = s_B[(ks*NT + nt)*32 + lane];
                    mma_bf16(acc[nt], aH[ks], B.x, B.y);   // Ah*Bh
                    mma_bf16(acc[nt], aH[ks], B.z, B.w);   // Ah*Bl
                    mma_bf16(acc[nt], aL[ks], B.x, B.y);   // Al*Bh
                }
            }
        }
    }

    // epilogue
    if (wid < 7) {
        const int m0 = wid*16 + r;
        const int vox = (h*WW + w)*TTT + m0;
        #pragma unroll
        for (int nt = 0; nt < NT; nt++) {
            #pragma unroll
            for (int j = 0; j < 2; j++) {
                int n = nt*8 + 2*q + j;
                if (n < COUT) {
                    float b = bias[n];
                    float v0 = acc[nt][j]   + b;
                    float v1 = acc[nt][2+j] + b;
                    if (RELU) { v0 = fmaxf(v0, 0.0f); v1 = fmaxf(v1, 0.0f); }
                    out[n*NS + vox]     = v0;
                    out[n*NS + vox + 8] = v1;
                }
            }
        }
    }
}

// ---------------------------------------------------------------------------
// fp32 direct conv (conv2a/2b/f) — proven in R1
// ---------------------------------------------------------------------------
template<int CIN, int CP, int COUT, bool RELU, bool ADD>
__global__ void __launch_bounds__(256)
conv3_kernel(const float* __restrict__ in, const float2* __restrict__ wp,
             const float* __restrict__ bias, const float* __restrict__ addsrc,
             float* __restrict__ out)
{
    __shared__ float  s_in[6*10*10];
    __shared__ float2 s_w[27*CP];
    const int tid = threadIdx.x;
    const int t0 = blockIdx.x*8, w0 = blockIdx.y*8, h0 = blockIdx.z*4;
    const int lt = tid & 7, lw = (tid >> 3) & 7, lh = tid >> 6;

    unsigned long long acc[CP];
    #pragma unroll
    for (int i = 0; i < CP; i++) acc[i] = 0ull;

    for (int ci = 0; ci < CIN; ci++) {
        __syncthreads();
        const float* inc = in + ci*NS;
        for (int i = tid; i < 600; i += 256) {
            int it = i % 10, iw = (i/10) % 10, ih = i/100;
            int gh = h0 + ih - 1, gw = w0 + iw - 1, gt = t0 + it - 1;
            float v = 0.0f;
            if ((unsigned)gh < HH && (unsigned)gw < WW && (unsigned)gt < TTT)
                v = inc[(gh*WW + gw)*TTT + gt];
            s_in[i] = v;
        }
        const float2* wc = wp + ci*27*CP;
        for (int i = tid; i < 27*CP; i += 256) s_w[i] = wc[i];
        __syncthreads();

        const unsigned long long* wq = reinterpret_cast<const unsigned long long*>(s_w);
        #pragma unroll
        for (int tap = 0; tap < 27; tap++) {
            const int dt = tap % 3, dw = (tap/3) % 3, dh = tap/9;
            float v = s_in[((lh+dh)*10 + (lw+dw))*10 + (lt+dt)];
            unsigned int vu = __float_as_uint(v);
            unsigned long long vv;
            asm("mov.b64 %0, {%1, %1};" : "=l"(vv) : "r"(vu));
            #pragma unroll
            for (int cp = 0; cp < CP; cp++) {
                asm("fma.rn.f32x2 %0, %1, %2, %0;"
                    : "+l"(acc[cp]) : "l"(wq[tap*CP + cp]), "l"(vv));
            }
        }
    }

    const int vox = ((h0+lh)*WW + (w0+lw))*TTT + (t0+lt);
    #pragma unroll
    for (int cp = 0; cp < CP; cp++) {
        float r0 = __uint_as_float((unsigned int)(acc[cp] & 0xffffffffull));
        float r1 = __uint_as_float((unsigned int)(acc[cp] >> 32));
        const int co0 = 2*cp, co1 = 2*cp+1;
        if (co0 < COUT) {
            float r = r0 + bias[co0];
            if (RELU) r = fmaxf(r, 0.0f);
            if (ADD)  r += addsrc[co0*NS + vox];
            out[co0*NS + vox] = r;
        }
        if (co1 < COUT) {
            float r = r1 + bias[co1];
            if (RELU) r = fmaxf(r, 0.0f);
            if (ADD)  r += addsrc[co1*NS + vox];
            out[co1*NS + vox] = r;
        }
    }
}

// ---------------------------------------------------------------------------
extern "C" void kernel_launch(void* const* d_in, const int* in_sizes, int n_in,
                              void* d_out, int out_size)
{
    const float* x    = (const float*)d_in[0];
    const float* y    = (const float*)d_in[1];
    const float* flow = (const float*)d_in[2];
    const float* w1a  = (const float*)d_in[3];
    const float* b1a  = (const float*)d_in[4];
    const float* w1b  = (const float*)d_in[5];
    const float* b1b  = (const float*)d_in[6];
    const float* w2a  = (const float*)d_in[7];
    const float* b2a  = (const float*)d_in[8];
    const float* w2b  = (const float*)d_in[9];
    const float* b2b  = (const float*)d_in[10];
    const float* wf   = (const float*)d_in[11];
    const float* bf   = (const float*)d_in[12];
    float* out = (float*)d_out;

    void *p_stack, *p_t1, *p_h, *p_t2, *p_hr, *p_Bf1a, *p_Bf1b;
    void *p_wp2a, *p_wp2b, *p_wpf;
    cudaGetSymbolAddress(&p_stack, g_stack);
    cudaGetSymbolAddress(&p_t1,    g_t1);
    cudaGetSymbolAddress(&p_h,     g_h);
    cudaGetSymbolAddress(&p_t2,    g_t2);
    cudaGetSymbolAddress(&p_hr,    g_hr);
    cudaGetSymbolAddress(&p_Bf1a,  g_Bf1a);
    cudaGetSymbolAddress(&p_Bf1b,  g_Bf1b);
    cudaGetSymbolAddress(&p_wp2a,  g_wp2a);
    cudaGetSymbolAddress(&p_wp2b,  g_wp2b);
    cudaGetSymbolAddress(&p_wpf,   g_wpf);

    // 1: repack (single kernel)
    repack_all<<<166, 256>>>(w1a, w1b, w2a, w2b, wf);
    // 2: warp
    warp_kernel<<<(NS + 255)/256, 256>>>(x, y, flow);
    // 3,4: box sums
    box_pm_kernel<<<dim3((NS + 255)/256, NC), 256>>>();
    box_pf_kernel<<<dim3((NSP + 255)/256, NC), 256>>>(y);
    // 5: correlation
    corr_kernel<<<(NS + 127)/128, 128>>>();

    dim3 mgrid(WW, HH);
    // 6: conv1a (mma.sync)  [ncu -s 5 profiles this]
    conv_mma<8,59,false><<<mgrid, 256>>>(
        (const float*)p_stack, (const uint4*)p_Bf1a, b1a, (float*)p_t1);
    // 7: conv1b (mma.sync) + relu
    conv_mma<2,16,true><<<mgrid, 256>>>(
        (const float*)p_t1, (const uint4*)p_Bf1b, b1b, (float*)p_h);

    dim3 cgrid(TTT/8, WW/8, HH/4);
    // 8: conv2a
    conv3_kernel<16,8,16,false,false><<<cgrid, 256>>>(
        (const float*)p_h, (const float2*)p_wp2a, b2a, nullptr, (float*)p_t2);
    // 9: conv2b: hr = h + relu(conv(t2))
    conv3_kernel<16,8,16,true,true><<<cgrid, 256>>>(
        (const float*)p_t2, (const float2*)p_wp2b, b2b, (const float*)p_h, (float*)p_hr);
    // 10: convf
    conv3_kernel<16,2,3,false,false><<<cgrid, 256>>>(
        (const float*)p_hr, (const float2*)p_wpf, bf, nullptr, out);
}

// round 5
// speedup vs baseline: 1.8854x; 1.0120x over previous
#include <cuda_runtime.h>
#include <cuda_bf16.h>
#include <cstdint>

#define HH 80
#define WW 96
#define TTT 112
#define NS (HH*WW*TTT)
#define NC 16
#define NCC 59
#define FH 40
#define FW 48
#define FT 56
#define PH 84
#define PW 100
#define PT 116
#define NSP (PH*PW*PT)

// scratch
__device__ float g_stack[NCC*NS];
__device__ float g_pm[NC*NS];
__device__ float g_pf[NC*NSP];
__device__ float g_t1[NCC*NS];
__device__ float g_h [NC*NS];
__device__ float g_t2[NC*NS];
__device__ float g_hr[NC*NS];

// B in mma-fragment order: [iter][ks3][nt][lane32] -> uint4 (b0h,b1h,b0l,b1l)
__device__ uint4 g_Bf1a[36*3*8*32];   // conv1a: NCH=4, NT=8
__device__ uint4 g_Bf1b[36*3*2*32];   // conv1b: NCH=4, NT=2
__device__ uint4 g_Bf2a[9*3*2*32];    // conv2a: NCH=1, NT=2
__device__ uint4 g_Bf2b[9*3*2*32];    // conv2b
__device__ uint4 g_Bff [9*3*1*32];    // convf : NT=1

// ---- helpers ----
__device__ __forceinline__ void split_pair(float v0, float v1, uint32_t& hi, uint32_t& lo) {
    uint32_t u0 = __float_as_uint(v0), u1 = __float_as_uint(v1);
    asm("prmt.b32 %0, %1, %2, 0x7632;" : "=r"(hi) : "r"(u0), "r"(u1));
    float h0 = __uint_as_float(u0 & 0xffff0000u);
    float h1 = __uint_as_float(u1 & 0xffff0000u);
    float l0 = v0 - h0, l1 = v1 - h1;
    asm("cvt.rn.satfinite.bf16x2.f32 %0, %1, %2;" : "=r"(lo) : "f"(l1), "f"(l0));
}

__device__ __forceinline__ void mma_bf16(float* c, const uint32_t* a, uint32_t b0, uint32_t b1) {
    asm volatile("mma.sync.aligned.m16n8k16.row.col.f32.bf16.bf16.f32 "
        "{%0,%1,%2,%3}, {%4,%5,%6,%7}, {%8,%9}, {%0,%1,%2,%3};"
        : "+f"(c[0]), "+f"(c[1]), "+f"(c[2]), "+f"(c[3])
        : "r"(a[0]), "r"(a[1]), "r"(a[2]), "r"(a[3]), "r"(b0), "r"(b1));
}

// ---------------------------------------------------------------------------
// repack all B fragments (same per-fragment layout as R4, proven)
// ---------------------------------------------------------------------------
__device__ void repack_one(int idx, const float* __restrict__ w, uint4* __restrict__ dst,
                           int NT, int NCH, int CIN, int COUT)
{
    int lane = idx & 31;
    int rest = idx >> 5;
    int nt = rest % NT;   rest /= NT;
    int ks = rest % 3;    rest /= 3;
    int iter = rest;
    int tap = iter / NCH, chunk = iter % NCH;
    int n = nt*8 + (lane >> 2);
    int q = lane & 3;
    int dh = tap/3, dw = tap%3;

    float v[4];
    #pragma unroll
    for (int j = 0; j < 4; j++) {
        int k = ks*16 + q*2 + (j >> 1)*8 + (j & 1);
        int cil = k/3, dt = k - 3*cil;
        int ci = chunk*16 + cil;
        float val = 0.0f;
        if (ci < CIN && n < COUT)
            val = w[(n*CIN + ci)*27 + dh*9 + dw*3 + dt];
        v[j] = val;
    }
    uint32_t h0, l0, h1, l1;
    split_pair(v[0], v[1], h0, l0);
    split_pair(v[2], v[3], h1, l1);
    dst[idx] = make_uint4(h0, h1, l0, l1);
}

__global__ void repack_all(const float* __restrict__ w1a, const float* __restrict__ w1b,
                           const float* __restrict__ w2a, const float* __restrict__ w2b,
                           const float* __restrict__ wf)
{
    int gi = blockIdx.x*256 + threadIdx.x;
    if      (gi < 27648)                 repack_one(gi,          w1a, g_Bf1a, 8, 4, 59, 59);
    else if (gi < 27648+6912)            repack_one(gi-27648,    w1b, g_Bf1b, 2, 4, 59, 16);
    else if (gi < 27648+6912+1728)       repack_one(gi-34560,    w2a, g_Bf2a, 2, 1, 16, 16);
    else if (gi < 27648+6912+3456)       repack_one(gi-36288,    w2b, g_Bf2b, 2, 1, 16, 16);
    else if (gi < 27648+6912+3456+864)   repack_one(gi-38016,    wf,  g_Bff,  1, 1, 16, 3);
}

// ---------------------------------------------------------------------------
// warp / box / corr  (proven)
// ---------------------------------------------------------------------------
__global__ void warp_kernel(const float* __restrict__ x, const float* __restrict__ y,
                            const float* __restrict__ flow)
{
    int idx = blockIdx.x*256 + threadIdx.x;
    if (idx >= NS) return;
    int t = idx % TTT, w = (idx / TTT) % WW, h = idx / (TTT*WW);

    float ph = h * (39.0f/79.0f), pw = w * (47.0f/95.0f), pt = t * (55.0f/111.0f);
    int ih = (int)ph; if (ih > FH-2) ih = FH-2;
    int iw = (int)pw; if (iw > FW-2) iw = FW-2;
    int it = (int)pt; if (it > FT-2) it = FT-2;
    float fh = ph - (float)ih, fw = pw - (float)iw, ft = pt - (float)it;

    float fu[3];
    #pragma unroll
    for (int c = 0; c < 3; c++) {
        const float* fc = flow + c*(FH*FW*FT) + (ih*FW + iw)*FT + it;
        float v000 = fc[0],        v001 = fc[1];
        float v010 = fc[FT],       v011 = fc[FT+1];
        float v100 = fc[FW*FT],    v101 = fc[FW*FT+1];
        float v110 = fc[FW*FT+FT], v111 = fc[FW*FT+FT+1];
        float a0 = v000*(1.0f-ft) + v001*ft;
        float a1 = v010*(1.0f-ft) + v011*ft;
        float a2 = v100*(1.0f-ft) + v101*ft;
        float a3 = v110*(1.0f-ft) + v111*ft;
        float b0 = a0*(1.0f-fw) + a1*fw;
        float b1 = a2*(1.0f-fw) + a3*fw;
        fu[c] = 2.0f*(b0*(1.0f-fh) + b1*fh);
    }

    float cx = (float)h + fu[0], cy = (float)w + fu[1], cz = (float)t + fu[2];
    float x0f = floorf(cx), y0f = floorf(cy), z0f = floorf(cz);
    float fx = cx - x0f, fy = cy - y0f, fz = cz - z0f;
    int x0 = (int)x0f, y0 = (int)y0f, z0 = (int)z0f;

    float acc[NC];
    #pragma unroll
    for (int c = 0; c < NC; c++) acc[c] = 0.0f;
    #pragma unroll
    for (int dx = 0; dx < 2; dx++)
    #pragma unroll
    for (int dy = 0; dy < 2; dy++)
    #pragma unroll
    for (int dz = 0; dz < 2; dz++) {
        int ix = x0+dx, iy = y0+dy, iz = z0+dz;
        if (ix < 0 || ix >= HH || iy < 0 || iy >= WW || iz < 0 || iz >= TTT) continue;
        float wgt = (dx ? fx : 1.0f-fx) * (dy ? fy : 1.0f-fy) * (dz ? fz : 1.0f-fz);
        const float* xp = x + (ix*WW + iy)*TTT + iz;
        #pragma unroll
        for (int c = 0; c < NC; c++) acc[c] += wgt * xp[c*NS];
    }
    #pragma unroll
    for (int c = 0; c < NC; c++) {
        g_stack[c*NS + idx]      = acc[c];
        g_stack[(43+c)*NS + idx] = y[c*NS + idx];
    }
}

__global__ void box_pm_kernel()
{
    int idx = blockIdx.x*256 + threadIdx.x;
    int c = blockIdx.y;
    if (idx >= NS) return;
    int t = idx % TTT, w = (idx / TTT) % WW, h = idx / (TTT*WW);
    const float* s = g_stack + c*NS;
    float acc = 0.0f;
    #pragma unroll
    for (int dh = -1; dh <= 1; dh++) {
        int gh = h + dh; if ((unsigned)gh >= HH) continue;
        #pragma unroll
        for (int dw = -1; dw <= 1; dw++) {
            int gw = w + dw; if ((unsigned)gw >= WW) continue;
            const float* row = s + (gh*WW + gw)*TTT;
            #pragma unroll
            for (int dt = -1; dt <= 1; dt++) {
                int gt = t + dt; if ((unsigned)gt >= TTT) continue;
                acc += row[gt];
            }
        }
    }
    g_pm[c*NS + idx] = acc;
}

__global__ void box_pf_kernel(const float* __restrict__ y)
{
    int idx = blockIdx.x*256 + threadIdx.x;
    int c = blockIdx.y;
    if (idx >= NSP) return;
    int d = idx % PT, b = (idx / PT) % PW, a = idx / (PT*PW);
    int hc = a - 2, wc = b - 2, tc = d - 2;
    const float* s = y + c*NS;
    float acc = 0.0f;
    #pragma unroll
    for (int dh = -1; dh <= 1; dh++) {
        int gh = hc + dh; if ((unsigned)gh >= HH) continue;
        #pragma unroll
        for (int dw = -1; dw <= 1; dw++) {
            int gw = wc + dw; if ((unsigned)gw >= WW) continue;
            const float* row = s + (gh*WW + gw)*TTT;
            #pragma unroll
            for (int dt = -1; dt <= 1; dt++) {
                int gt = tc + dt; if ((unsigned)gt >= TTT) continue;
                acc += row[gt];
            }
        }
    }
    g_pf[c*NSP + idx] = acc;
}

__global__ void corr_kernel()
{
    int idx = blockIdx.x*128 + threadIdx.x;
    if (idx >= NS) return;
    int t = idx % TTT, w = (idx / TTT) % WW, h = idx / (TTT*WW);
    float pm[NC];
    #pragma unroll
    for (int c = 0; c < NC; c++) pm[c] = g_pm[c*NS + idx];
    int o = 0;
    for (int i = 0; i < 3; i++)
    for (int j = 0; j < 3; j++)
    for (int k = 0; k < 3; k++) {
        const float* p = g_pf + ((h + 2*i)*PW + (w + 2*j))*PT + (t + 2*k);
        float acc = 0.0f;
        #pragma unroll
        for (int c = 0; c < NC; c++) acc += pm[c] * p[c*NSP];
        g_stack[(16 + o)*NS + idx] = acc * (1.0f/27.0f);
        o++;
    }
}

// ---------------------------------------------------------------------------
// warp-MMA implicit-GEMM conv v2: 2 columns/CTA, 2 m-tiles/warp (B reg reuse).
// CTA = (2 cols at w0,w0+1) x M=112; warps 0..6 compute tile i for both cols.
// K loop: 9 taps x NCH chunks, K=48 per iter (3 k-steps). Same B layout as R4.
// ---------------------------------------------------------------------------
template<int NCH, int NT, int CINR, int COUT, bool RELU, bool ADD>
__global__ void __launch_bounds__(256)
conv_mma2(const float* __restrict__ in, const uint4* __restrict__ Bf,
          const float* __restrict__ bias, const float* __restrict__ addsrc,
          float* __restrict__ out)
{
    __shared__ float s_strip[2*16*121 + 8];
    __shared__ uint4 s_B[3*NT*32];

    const int tid = threadIdx.x, wid = tid >> 5, lane = tid & 31;
    const int w0 = blockIdx.x*2, h = blockIdx.y;
    const int q = lane & 3, r = lane >> 2;

    float acc0[NT][4], acc1[NT][4];
    #pragma unroll
    for (int nt = 0; nt < NT; nt++)
        #pragma unroll
        for (int j = 0; j < 4; j++) { acc0[nt][j] = 0.0f; acc1[nt][j] = 0.0f; }

    for (int iter = 0; iter < 9*NCH; iter++) {
        const int tap = iter / NCH, chunk = iter % NCH;
        const int gh = h + tap/3 - 1;
        const int gwb = w0 + tap%3 - 1;            // slot0 col, slot1 = gwb+1
        const bool hok = ((unsigned)gh < HH);

        __syncthreads();
        // stage 2 strips x 16 ch x 114 (t = -1..112)
        for (int i = tid; i < 2*16*114; i += 256) {
            int slot = i / 1824;
            int rem  = i - slot*1824;
            int cil  = rem / 114, tt = rem - cil*114;
            int ci = chunk*16 + cil;
            int gw = gwb + slot;
            int t = tt - 1;
            float v = 0.0f;
            if (hok && (unsigned)gw < WW && ci < CINR && (unsigned)t < TTT)
                v = in[ci*NS + (gh*WW + gw)*TTT + t];
            s_strip[slot*1936 + cil*121 + tt] = v;
        }
        // stage B fragments for this iter
        {
            const uint4* src = Bf + iter*(3*NT*32);
            #pragma unroll
            for (int i = tid; i < 3*NT*32; i += 256) s_B[i] = src[i];
        }
        __syncthreads();

        if (wid < 7) {
            const int m0 = wid*16 + r;
            #pragma unroll
            for (int ks = 0; ks < 3; ks++) {
                const int kb = ks*16 + q*2;
                uint32_t aH0[4], aL0[4], aH1[4], aL1[4];
                #pragma unroll
                for (int half = 0; half < 2; half++) {
                    int k  = kb + half*8;
                    int c0 = (k*171) >> 9,  d0 = k - 3*c0;
                    int k1 = k + 1;
                    int c1 = (k1*171) >> 9, d1 = k1 - 3*c1;
                    int o00 = c0*121 + m0 + d0;
                    int o01 = c1*121 + m0 + d1;
                    // tile 0 (col w0)
                    float v00 = s_strip[o00];
                    float v01 = s_strip[o01];
                    float v10 = s_strip[o00 + 8];
                    float v11 = s_strip[o01 + 8];
                    split_pair(v00, v01, aH0[half*2+0], aL0[half*2+0]);
                    split_pair(v10, v11, aH0[half*2+1], aL0[half*2+1]);
                    // tile 1 (col w0+1)
                    float u00 = s_strip[1936 + o00];
                    float u01 = s_strip[1936 + o01];
                    float u10 = s_strip[1936 + o00 + 8];
                    float u11 = s_strip[1936 + o01 + 8];
                    split_pair(u00, u01, aH1[half*2+0], aL1[half*2+0]);
                    split_pair(u10, u11, aH1[half*2+1], aL1[half*2+1]);
                }
                #pragma unroll
                for (int nt = 0; nt < NT; nt++) {
                    uint4 B = s_B[(ks*NT + nt)*32 + lane];
                    mma_bf16(acc0[nt], aH0, B.x, B.y);
                    mma_bf16(acc0[nt], aH0, B.z, B.w);
                    mma_bf16(acc0[nt], aL0, B.x, B.y);
                    mma_bf16(acc1[nt], aH1, B.x, B.y);
                    mma_bf16(acc1[nt], aH1, B.z, B.w);
                    mma_bf16(acc1[nt], aL1, B.x, B.y);
                }
            }
        }
    }

    // epilogue: write both columns
    if (wid < 7) {
        const int m0 = wid*16 + r;
        #pragma unroll
        for (int tile = 0; tile < 2; tile++) {
            const int vox = (h*WW + (w0 + tile))*TTT + m0;
            #pragma unroll
            for (int nt = 0; nt < NT; nt++) {
                #pragma unroll
                for (int j = 0; j < 2; j++) {
                    int n = nt*8 + 2*q + j;
                    if (n < COUT) {
                        float b = bias[n];
                        float v0 = (tile ? acc1[nt][j]   : acc0[nt][j])   + b;
                        float v1 = (tile ? acc1[nt][2+j] : acc0[nt][2+j]) + b;
                        if (RELU) { v0 = fmaxf(v0, 0.0f); v1 = fmaxf(v1, 0.0f); }
                        if (ADD)  { v0 += addsrc[n*NS + vox]; v1 += addsrc[n*NS + vox + 8]; }
                        out[n*NS + vox]     = v0;
                        out[n*NS + vox + 8] = v1;
                    }
                }
            }
        }
    }
}

// ---------------------------------------------------------------------------
extern "C" void kernel_launch(void* const* d_in, const int* in_sizes, int n_in,
                              void* d_out, int out_size)
{
    const float* x    = (const float*)d_in[0];
    const float* y    = (const float*)d_in[1];
    const float* flow = (const float*)d_in[2];
    const float* w1a  = (const float*)d_in[3];
    const float* b1a  = (const float*)d_in[4];
    const float* w1b  = (const float*)d_in[5];
    const float* b1b  = (const float*)d_in[6];
    const float* w2a  = (const float*)d_in[7];
    const float* b2a  = (const float*)d_in[8];
    const float* w2b  = (const float*)d_in[9];
    const float* b2b  = (const float*)d_in[10];
    const float* wf   = (const float*)d_in[11];
    const float* bf   = (const float*)d_in[12];
    float* out = (float*)d_out;

    void *p_stack, *p_t1, *p_h, *p_t2, *p_hr;
    void *p_Bf1a, *p_Bf1b, *p_Bf2a, *p_Bf2b, *p_Bff;
    cudaGetSymbolAddress(&p_stack, g_stack);
    cudaGetSymbolAddress(&p_t1,    g_t1);
    cudaGetSymbolAddress(&p_h,     g_h);
    cudaGetSymbolAddress(&p_t2,    g_t2);
    cudaGetSymbolAddress(&p_hr,    g_hr);
    cudaGetSymbolAddress(&p_Bf1a,  g_Bf1a);
    cudaGetSymbolAddress(&p_Bf1b,  g_Bf1b);
    cudaGetSymbolAddress(&p_Bf2a,  g_Bf2a);
    cudaGetSymbolAddress(&p_Bf2b,  g_Bf2b);
    cudaGetSymbolAddress(&p_Bff,   g_Bff);

    // 1: repack (38880 fragment slots)
    repack_all<<<152, 256>>>(w1a, w1b, w2a, w2b, wf);
    // 2: warp
    warp_kernel<<<(NS + 255)/256, 256>>>(x, y, flow);
    // 3,4: box sums
    box_pm_kernel<<<dim3((NS + 255)/256, NC), 256>>>();
    box_pf_kernel<<<dim3((NSP + 255)/256, NC), 256>>>(y);
    // 5: correlation
    corr_kernel<<<(NS + 127)/128, 128>>>();

    dim3 mgrid(WW/2, HH);   // 48 x 80
    // 6: conv1a  [ncu -s 5 profiles this]
    conv_mma2<4,8,59,59,false,false><<<mgrid, 256>>>(
        (const float*)p_stack, (const uint4*)p_Bf1a, b1a, nullptr, (float*)p_t1);
    // 7: conv1b + relu
    conv_mma2<4,2,59,16,true,false><<<mgrid, 256>>>(
        (const float*)p_t1, (const uint4*)p_Bf1b, b1b, nullptr, (float*)p_h);
    // 8: conv2a
    conv_mma2<1,2,16,16,false,false><<<mgrid, 256>>>(
        (const float*)p_h, (const uint4*)p_Bf2a, b2a, nullptr, (float*)p_t2);
    // 9: conv2b: hr = h + relu(conv(t2)+b)
    conv_mma2<1,2,16,16,true,true><<<mgrid, 256>>>(
        (const float*)p_t2, (const uint4*)p_Bf2b, b2b, (const float*)p_h, (float*)p_hr);
    // 10: convf
    conv_mma2<1,1,16,3,false,false><<<mgrid, 256>>>(
        (const float*)p_hr, (const uint4*)p_Bff, bf, nullptr, out);
}